// round 6
// baseline (speedup 1.0000x reference)
#include <cuda_runtime.h>
#include <math.h>

// Shapes: logits (4, 257, 131072) f32, advantages (4,) f32,
//         input_ids (4, 257) i32, labels (4, 257) i32
// Output: [loss(1) | per_token_logps(4*256) | avg_entropy_per_sample(4) | avg_entropy_truncated(4)]
//         = 1033 floats

#define THREADS 512
constexpr int BB  = 4;
constexpr int TT  = 257;
constexpr int TM1 = 256;
constexpr int VV  = 131072;
// analytic correction: -sum p*log(p+eps) = H - sum p*log1p(eps/p) ~= H - V*eps
constexpr float ENT_CORR = 131072.0f * 1e-9f;

__device__ float g_H[BB * TM1];  // token_entropy scratch

__global__ __launch_bounds__(THREADS) void row_kernel(
    const float* __restrict__ logits,
    const int*   __restrict__ input_ids,
    float*       __restrict__ out)
{
    const int row = blockIdx.x;          // 0..1023
    const int b = row >> 8;
    const int t = row & 255;
    const size_t row_off = (size_t)(b * TT + t) * VV;
    const float4* rp = reinterpret_cast<const float4*>(logits + row_off);

    float s = 0.0f;   // sum exp(x)
    float w = 0.0f;   // sum x * exp(x)

    const int tid = threadIdx.x;
    // V/4 = 32768 float4 per row. Process 2 float4 per thread per iter
    // (batched loads -> higher MLP), 32 iters per thread.
    #pragma unroll 4
    for (int k = tid; k < VV / 8; k += THREADS) {
        float4 v0 = rp[k];
        float4 v1 = rp[k + VV / 8];
        float e0 = __expf(v0.x);
        float e1 = __expf(v0.y);
        float e2 = __expf(v0.z);
        float e3 = __expf(v0.w);
        float e4 = __expf(v1.x);
        float e5 = __expf(v1.y);
        float e6 = __expf(v1.z);
        float e7 = __expf(v1.w);
        s += ((e0 + e1) + (e2 + e3)) + ((e4 + e5) + (e6 + e7));
        w = fmaf(v0.x, e0, w);
        w = fmaf(v0.y, e1, w);
        w = fmaf(v0.z, e2, w);
        w = fmaf(v0.w, e3, w);
        w = fmaf(v1.x, e4, w);
        w = fmaf(v1.y, e5, w);
        w = fmaf(v1.z, e6, w);
        w = fmaf(v1.w, e7, w);
    }

    // warp reduction
    #pragma unroll
    for (int off = 16; off; off >>= 1) {
        s += __shfl_down_sync(0xffffffff, s, off);
        w += __shfl_down_sync(0xffffffff, w, off);
    }

    __shared__ float ss[16], sw[16];
    const int warp = tid >> 5;
    const int lane = tid & 31;
    if (lane == 0) { ss[warp] = s; sw[warp] = w; }
    __syncthreads();

    if (warp == 0) {
        s = (lane < 16) ? ss[lane] : 0.0f;
        w = (lane < 16) ? sw[lane] : 0.0f;
        #pragma unroll
        for (int off = 8; off; off >>= 1) {
            s += __shfl_down_sync(0xffffffff, s, off);
            w += __shfl_down_sync(0xffffffff, w, off);
        }
        if (lane == 0) {
            const int chosen = input_ids[b * TT + t + 1];
            const float xc = logits[row_off + (size_t)chosen];
            const float lse = logf(s);
            out[1 + row] = xc - lse;                   // per_token_logps (TEMP=1)
            g_H[row] = lse - w / s - ENT_CORR;         // token_entropy
        }
    }
}

__global__ void finalize_kernel(
    const float* __restrict__ advantages,
    const int*   __restrict__ labels,
    float*       __restrict__ out)
{
    __shared__ float s_advm[BB];
    __shared__ float s_mask[BB];
    const int b = threadIdx.x;
    if (b < BB) {
        const float adv = advantages[b];
        float msum = 0.0f, Hsum = 0.0f, Htr = 0.0f, ntr = 0.0f;
        int cum = 0;
        for (int t = 0; t < TM1; t++) {
            const int lab = labels[b * TT + t + 1];
            const float m = (float)lab;
            const float H = g_H[b * TM1 + t];
            msum += m;
            Hsum += H * m;
            const bool valid = (lab == 1);
            cum += valid ? 1 : 0;
            const bool ecm = valid && (cum >= 4) && (cum <= 100);
            if (ecm) { Htr += H; ntr += 1.0f; }
        }
        out[1 + BB * TM1 + b]      = Hsum / msum;   // avg_entropy_per_sample
        out[1 + BB * TM1 + BB + b] = Htr / ntr;     // avg_entropy_truncated
        s_advm[b] = adv * msum;
        s_mask[b] = msum;
    }
    __syncthreads();
    if (threadIdx.x == 0) {
        float num = s_advm[0] + s_advm[1] + s_advm[2] + s_advm[3];
        float den = s_mask[0] + s_mask[1] + s_mask[2] + s_mask[3];
        // ratio == 1 exactly => clipped == 1 => per_token_loss = -adv[b]
        out[0] = -num / den;
    }
}

extern "C" void kernel_launch(void* const* d_in, const int* in_sizes, int n_in,
                              void* d_out, int out_size)
{
    const float* logits     = (const float*)d_in[0];
    const float* advantages = (const float*)d_in[1];
    const int*   input_ids  = (const int*)d_in[2];
    const int*   labels     = (const int*)d_in[3];
    float* out = (float*)d_out;

    row_kernel<<<BB * TM1, THREADS>>>(logits, input_ids, out);
    finalize_kernel<<<1, 32>>>(advantages, labels, out);
}

// round 7
// speedup vs baseline: 1.2547x; 1.2547x over previous
#include <cuda_runtime.h>
#include <math.h>

// Shapes: logits (4, 257, 131072) f32, advantages (4,) f32,
//         input_ids (4, 257) i32, labels (4, 257) i32
// Output: [loss(1) | per_token_logps(4*256) | avg_entropy_per_sample(4) | avg_entropy_truncated(4)]
//         = 1033 floats

#define THREADS 512
constexpr int BB  = 4;
constexpr int TT  = 257;
constexpr int TM1 = 256;
constexpr int VV  = 131072;
// analytic correction: -sum p*log(p+eps) = H - sum p*log1p(eps/p) ~= H - V*eps
constexpr float ENT_CORR = 131072.0f * 1e-9f;

__device__ float g_H[BB * TM1];  // token_entropy scratch

__global__ __launch_bounds__(THREADS) void row_kernel(
    const float* __restrict__ logits,
    const int*   __restrict__ input_ids,
    float*       __restrict__ out)
{
    const int row = blockIdx.x;          // 0..1023
    const int b = row >> 8;
    const int t = row & 255;
    const size_t row_off = (size_t)(b * TT + t) * VV;
    const float4* rp = reinterpret_cast<const float4*>(logits + row_off);

    float s = 0.0f;   // sum exp(x)
    float w = 0.0f;   // sum x * exp(x)

    const int tid = threadIdx.x;
    // V/4 = 32768 float4 per row; 2 float4 per thread per iter (high MLP).
    #pragma unroll 4
    for (int k = tid; k < VV / 8; k += THREADS) {
        float4 v0 = rp[k];
        float4 v1 = rp[k + VV / 8];
        float e0 = __expf(v0.x);
        float e1 = __expf(v0.y);
        float e2 = __expf(v0.z);
        float e3 = __expf(v0.w);
        float e4 = __expf(v1.x);
        float e5 = __expf(v1.y);
        float e6 = __expf(v1.z);
        float e7 = __expf(v1.w);
        s += ((e0 + e1) + (e2 + e3)) + ((e4 + e5) + (e6 + e7));
        w = fmaf(v0.x, e0, w);
        w = fmaf(v0.y, e1, w);
        w = fmaf(v0.z, e2, w);
        w = fmaf(v0.w, e3, w);
        w = fmaf(v1.x, e4, w);
        w = fmaf(v1.y, e5, w);
        w = fmaf(v1.z, e6, w);
        w = fmaf(v1.w, e7, w);
    }

    // warp reduction
    #pragma unroll
    for (int off = 16; off; off >>= 1) {
        s += __shfl_down_sync(0xffffffff, s, off);
        w += __shfl_down_sync(0xffffffff, w, off);
    }

    __shared__ float ss[16], sw[16];
    const int warp = tid >> 5;
    const int lane = tid & 31;
    if (lane == 0) { ss[warp] = s; sw[warp] = w; }
    __syncthreads();

    if (warp == 0) {
        s = (lane < 16) ? ss[lane] : 0.0f;
        w = (lane < 16) ? sw[lane] : 0.0f;
        #pragma unroll
        for (int off = 8; off; off >>= 1) {
            s += __shfl_down_sync(0xffffffff, s, off);
            w += __shfl_down_sync(0xffffffff, w, off);
        }
        if (lane == 0) {
            const int chosen = input_ids[b * TT + t + 1];
            const float xc = logits[row_off + (size_t)chosen];
            const float lse = logf(s);
            out[1 + row] = xc - lse;                   // per_token_logps (TEMP=1)
            g_H[row] = lse - w / s - ENT_CORR;         // token_entropy
        }
    }
}

// Parallel finalize: 1024 threads, one per (b, t).
__global__ __launch_bounds__(1024) void finalize_kernel(
    const float* __restrict__ advantages,
    const int*   __restrict__ labels,
    float*       __restrict__ out)
{
    const int tid  = threadIdx.x;          // 0..1023
    const int b    = tid >> 8;             // 0..3
    const int t    = tid & 255;            // 0..255
    const int wid  = tid >> 5;             // 0..31
    const int lane = tid & 31;

    const int   lab   = labels[b * TT + t + 1];
    const float H     = g_H[tid];
    const bool  valid = (lab == 1);

    // ---- segmented prefix sum of `valid` over each 256-wide batch segment ----
    const unsigned ballot = __ballot_sync(0xffffffffu, valid);
    const unsigned le_mask = (2u << lane) - 1u;       // lanes <= lane
    const int lane_prefix_incl = __popc(ballot & le_mask);
    const int warp_total = __popc(ballot);

    __shared__ int s_wcnt[32];
    if (lane == 0) s_wcnt[wid] = warp_total;
    __syncthreads();

    // warps 8*b .. 8*b+7 belong to batch b; sum totals of prior warps in segment
    int seg_base = 0;
    const int seg_w0 = wid & ~7;
    for (int j = seg_w0; j < wid; j++) seg_base += s_wcnt[j];
    const int cum = seg_base + lane_prefix_incl;      // inclusive cumsum

    const bool ecm = valid && (cum >= 4) && (cum <= 100);

    // ---- four masked reductions per batch ----
    float m  = valid ? 1.0f : 0.0f;
    float Hm = valid ? H : 0.0f;
    float He = ecm ? H : 0.0f;
    float ne = ecm ? 1.0f : 0.0f;
    #pragma unroll
    for (int off = 16; off; off >>= 1) {
        m  += __shfl_down_sync(0xffffffffu, m,  off);
        Hm += __shfl_down_sync(0xffffffffu, Hm, off);
        He += __shfl_down_sync(0xffffffffu, He, off);
        ne += __shfl_down_sync(0xffffffffu, ne, off);
    }

    __shared__ float s_m[BB], s_Hm[BB], s_He[BB], s_ne[BB];
    if (tid < BB)      { s_m[tid] = 0.f; s_Hm[tid] = 0.f; s_He[tid] = 0.f; s_ne[tid] = 0.f; }
    __syncthreads();
    if (lane == 0) {
        atomicAdd(&s_m[b],  m);
        atomicAdd(&s_Hm[b], Hm);
        atomicAdd(&s_He[b], He);
        atomicAdd(&s_ne[b], ne);
    }
    __syncthreads();

    if (tid < BB) {
        out[1 + BB * TM1 + tid]      = s_Hm[tid] / s_m[tid];   // avg_entropy_per_sample
        out[1 + BB * TM1 + BB + tid] = s_He[tid] / s_ne[tid];  // avg_entropy_truncated
    }
    if (tid == 0) {
        // ratio == 1 exactly => clipped == 1 => per_token_loss = -adv[b]
        float num = 0.f, den = 0.f;
        #pragma unroll
        for (int i = 0; i < BB; i++) {
            num += advantages[i] * s_m[i];
            den += s_m[i];
        }
        out[0] = -num / den;
    }
}

extern "C" void kernel_launch(void* const* d_in, const int* in_sizes, int n_in,
                              void* d_out, int out_size)
{
    const float* logits     = (const float*)d_in[0];
    const float* advantages = (const float*)d_in[1];
    const int*   input_ids  = (const int*)d_in[2];
    const int*   labels     = (const int*)d_in[3];
    float* out = (float*)d_out;

    row_kernel<<<BB * TM1, THREADS>>>(logits, input_ids, out);
    finalize_kernel<<<1, 1024>>>(advantages, labels, out);
}